// round 16
// baseline (speedup 1.0000x reference)
#include <cuda_runtime.h>
#include <cuda_bf16.h>
#include <cstdint>
#include <cstddef>

#define NT    4096      // H*W tokens
#define CH    256       // hidden channels
#define CIN   512       // input channels
#define BATCH 4
#define SROW  36        // smem row stride (words), ≡4 mod 32 -> conflict-free fragments

// ---------------- scratch (device globals; no allocation in kernel_launch) --------
__device__ __nv_bfloat16 d_fThi[(size_t)BATCH * NT * CH];  // fT hi [b][n][d]
__device__ __nv_bfloat16 d_fTlo[(size_t)BATCH * NT * CH];
__device__ __nv_bfloat16 d_gThi[(size_t)BATCH * NT * CH];  // gT hi [b][m][d]
__device__ __nv_bfloat16 d_gTlo[(size_t)BATCH * NT * CH];
__device__ float d_h  [(size_t)BATCH * CH * NT];   // h  [b][d][m]
__device__ float d_fcs[(size_t)BATCH * NT * CH];   // Fcs[b][n][d]
__device__ float d_S  [(size_t)BATCH * NT * NT];   // scores [b][n][m]
__device__ float d_soff[(size_t)BATCH * NT];       // per-row max + ln(sum)
__device__ float d_mean[2 * BATCH * CIN];
__device__ float d_inv [2 * BATCH * CIN];

__device__ __forceinline__ float relu6f(float x) { return fminf(fmaxf(x, 0.0f), 6.0f); }
__device__ __forceinline__ float tf32rna(float x) {
    float r; asm("cvt.rna.tf32.f32 %0, %1;" : "=f"(r) : "f"(x)); return r;
}
__device__ __forceinline__ uint32_t smem_u32(const void* p) {
    uint32_t a;
    asm("{ .reg .u64 t; cvta.to.shared.u64 t, %1; cvt.u32.u64 %0, t; }" : "=r"(a) : "l"(p));
    return a;
}
// m16n8k8 tf32 MMA (baseline PTX, sm_80+)
__device__ __forceinline__ void mma8(float* d, const uint32_t* a, const uint32_t* b) {
    asm volatile("mma.sync.aligned.m16n8k8.row.col.f32.tf32.tf32.f32 "
                 "{%0,%1,%2,%3},{%4,%5,%6,%7},{%8,%9},{%0,%1,%2,%3};"
                 : "+f"(d[0]), "+f"(d[1]), "+f"(d[2]), "+f"(d[3])
                 : "r"(a[0]), "r"(a[1]), "r"(a[2]), "r"(a[3]), "r"(b[0]), "r"(b[1]));
}
// m16n8k16 bf16 MMA (baseline PTX, sm_80+)
__device__ __forceinline__ void mma16(float* d, const uint32_t* a, const uint32_t* b) {
    asm volatile("mma.sync.aligned.m16n8k16.row.col.f32.bf16.bf16.f32 "
                 "{%0,%1,%2,%3},{%4,%5,%6,%7},{%8,%9},{%0,%1,%2,%3};"
                 : "+f"(d[0]), "+f"(d[1]), "+f"(d[2]), "+f"(d[3])
                 : "r"(a[0]), "r"(a[1]), "r"(a[2]), "r"(a[3]), "r"(b[0]), "r"(b[1]));
}

// Store 4 consecutive k floats of one tile row into smem.
// MODE 0: tf32-rounded floats at word col c4. MODE 1: bf16 hi/lo pairs (hi @c4/2, lo @+16).
template<int MODE>
__device__ __forceinline__ void tile_store(float* S, int r, int c4, float4 v) {
    if (MODE == 0) {
        v.x = tf32rna(v.x); v.y = tf32rna(v.y);
        v.z = tf32rna(v.z); v.w = tf32rna(v.w);
        *(float4*)(S + r * SROW + c4) = v;
    } else {
        __nv_bfloat162 h0 = __floats2bfloat162_rn(v.x, v.y);
        __nv_bfloat162 h1 = __floats2bfloat162_rn(v.z, v.w);
        float2 f0 = __bfloat1622float2(h0);
        float2 f1 = __bfloat1622float2(h1);
        __nv_bfloat162 l0 = __floats2bfloat162_rn(v.x - f0.x, v.y - f0.y);
        __nv_bfloat162 l1 = __floats2bfloat162_rn(v.z - f1.x, v.w - f1.y);
        uint32_t* W = (uint32_t*)(S + r * SROW) + (c4 >> 1);
        *(uint2*)(W)      = make_uint2(*(uint32_t*)&h0, *(uint32_t*)&h1);
        *(uint2*)(W + 16) = make_uint2(*(uint32_t*)&l0, *(uint32_t*)&l1);
    }
}

// ---------------- per-(b,c) instance-norm stats, ddof=1 ----------------
__global__ __launch_bounds__(256) void stats_kernel(const float* __restrict__ Fc,
                                                    const float* __restrict__ Fs) {
    int inst  = blockIdx.x;
    int which = blockIdx.y;
    const float* src = (which ? Fs : Fc) + (size_t)inst * NT;
    int tid = threadIdx.x;
    float s = 0.f, ss = 0.f;
    for (int e = tid; e < NT / 4; e += 256) {
        float4 v = ((const float4*)src)[e];
        s  += v.x + v.y + v.z + v.w;
        ss += v.x * v.x + v.y * v.y + v.z * v.z + v.w * v.w;
    }
    for (int o = 16; o; o >>= 1) {
        s  += __shfl_xor_sync(0xffffffffu, s, o);
        ss += __shfl_xor_sync(0xffffffffu, ss, o);
    }
    __shared__ float sb[8], ssb[8];
    if ((tid & 31) == 0) { sb[tid >> 5] = s; ssb[tid >> 5] = ss; }
    __syncthreads();
    if (tid == 0) {
        s = 0.f; ss = 0.f;
        for (int w = 0; w < 8; w++) { s += sb[w]; ss += ssb[w]; }
        float mean = s / (float)NT;
        float var  = (ss - s * mean) / (float)(NT - 1);
        d_mean[which * BATCH * CIN + inst] = mean;
        d_inv [which * BATCH * CIN + inst] = rsqrtf(var + 1e-5f);
    }
}

// ---------------- GEMM1: S[n][m] = sum_d (fhi+flo)[n,d] * (ghi+glo)[m,d] ----------
// Operands pre-split to bf16 hi/lo in gmem. cp.async 4-stage ring, 1 sync/chunk.
// CTA tile 128x128, 8 warps (32x64 warp tile).
__global__ __launch_bounds__(256, 1)
void attn_sgemm(const __nv_bfloat16* __restrict__ Ahi, const __nv_bfloat16* __restrict__ Alo,
                const __nv_bfloat16* __restrict__ Bhi, const __nv_bfloat16* __restrict__ Blo,
                float* __restrict__ Sg)
{
    constexpr int STG  = 4;
    constexpr int BUFW = 2 * 128 * SROW;          // words per stage (A tile then B tile)
    constexpr int NCH  = CH / 32;                 // 8 chunks
    extern __shared__ float smf[];

    const int tid = threadIdx.x;
    const int wid = tid >> 5, lane = tid & 31;
    const int wm  = wid & 3,  wn   = wid >> 2;
    const int lr  = lane >> 2, lc  = lane & 3;
    const int r2  = tid >> 1;                     // row 0..127
    const int hf  = tid & 1;                      // 0 -> hi array, 1 -> lo array

    const size_t aoff = ((size_t)blockIdx.z * NT + blockIdx.y * 128 + r2) * CH;
    const size_t boff = ((size_t)blockIdx.z * NT + blockIdx.x * 128 + r2) * CH;
    const __nv_bfloat16* gA = (hf ? Alo : Ahi) + aoff;
    const __nv_bfloat16* gB = (hf ? Blo : Bhi) + boff;

    const uint32_t sbase = smem_u32(smf);
    const uint32_t dA0 = sbase + (r2 * SROW + hf * 16) * 4;
    const uint32_t dB0 = dA0 + 128 * SROW * 4;

    auto issue = [&](int c, int stg) {
        uint32_t da = dA0 + stg * BUFW * 4;
        uint32_t db = dB0 + stg * BUFW * 4;
        const char* pa = (const char*)(gA + c * 32);
        const char* pb = (const char*)(gB + c * 32);
#pragma unroll
        for (int g = 0; g < 4; g++) {
            asm volatile("cp.async.cg.shared.global [%0], [%1], 16;"
                         :: "r"(da + g * 16), "l"(pa + g * 16));
            asm volatile("cp.async.cg.shared.global [%0], [%1], 16;"
                         :: "r"(db + g * 16), "l"(pb + g * 16));
        }
        asm volatile("cp.async.commit_group;");
    };

    float acc[2][8][4];
#pragma unroll
    for (int mi = 0; mi < 2; mi++)
#pragma unroll
        for (int nj = 0; nj < 8; nj++)
#pragma unroll
            for (int q = 0; q < 4; q++) acc[mi][nj][q] = 0.f;

    issue(0, 0); issue(1, 1); issue(2, 2);

    for (int c = 0; c < NCH; c++) {
        asm volatile("cp.async.wait_group 2;" ::: "memory");
        __syncthreads();
        const uint32_t* UA = (const uint32_t*)(smf + (c % STG) * BUFW);
        const uint32_t* UB = UA + 128 * SROW;
#pragma unroll
        for (int s = 0; s < 2; s++) {
            const int k0 = s * 8;
            uint32_t ah[2][4], al[2][4], bh[8][2], bl[8][2];
#pragma unroll
            for (int mi = 0; mi < 2; mi++) {
                int base = (wm * 32 + mi * 16 + lr) * SROW + k0 + lc;
                ah[mi][0] = UA[base];            ah[mi][1] = UA[base + 8 * SROW];
                ah[mi][2] = UA[base + 4];        ah[mi][3] = UA[base + 8 * SROW + 4];
                al[mi][0] = UA[base + 16];       al[mi][1] = UA[base + 8 * SROW + 16];
                al[mi][2] = UA[base + 20];       al[mi][3] = UA[base + 8 * SROW + 20];
            }
#pragma unroll
            for (int nj = 0; nj < 8; nj++) {
                int base = (wn * 64 + nj * 8 + lr) * SROW + k0 + lc;
                bh[nj][0] = UB[base];            bh[nj][1] = UB[base + 4];
                bl[nj][0] = UB[base + 16];       bl[nj][1] = UB[base + 20];
            }
#pragma unroll
            for (int mi = 0; mi < 2; mi++)
#pragma unroll
                for (int nj = 0; nj < 8; nj++) {
                    mma16(acc[mi][nj], ah[mi], bh[nj]);
                    mma16(acc[mi][nj], ah[mi], bl[nj]);
                    mma16(acc[mi][nj], al[mi], bh[nj]);
                }
        }
        if (c + 3 < NCH) issue(c + 3, (c + 3) % STG);
    }

    float* C = Sg + (size_t)blockIdx.z * NT * NT + (size_t)(blockIdx.y * 128) * NT
                  + blockIdx.x * 128;
#pragma unroll
    for (int mi = 0; mi < 2; mi++) {
        int r = wm * 32 + mi * 16 + lr;
#pragma unroll
        for (int nj = 0; nj < 8; nj++) {
            int col = wn * 64 + nj * 8 + lc * 2;
            *(float2*)(C + (size_t)r * NT + col)       = make_float2(acc[mi][nj][0], acc[mi][nj][1]);
            *(float2*)(C + (size_t)(r + 8) * NT + col) = make_float2(acc[mi][nj][2], acc[mi][nj][3]);
        }
    }
}

// ---------------- MMA GEMM: C[M,N] = A[M,K] * B[N,K]^T (R14 version) -------------
// CTA tile 128x128, K-chunk 32, 8 warps, dbl-buffer. MODE0: single tf32.
// EXPA: A -> exp(a - aoff[row]) at smem-store time.
template<int MODE, int ACT, int EXPA>
__global__ __launch_bounds__(256, 1)
void mma_gemm(const float* __restrict__ Ag, const float* __restrict__ Bg,
              const float* __restrict__ bias, const float* __restrict__ aoffg,
              float* __restrict__ Cg,
              int K, int lda, int ldb, int ldc,
              size_t bA, size_t bB, size_t bC)
{
    constexpr int TBUF = 128 * SROW;
    extern __shared__ float smf[];
    float* SAbase = smf;
    float* SBbase = smf + 2 * TBUF;

    const int tid  = threadIdx.x;
    const int wid  = tid >> 5, lane = tid & 31;
    const int wm   = wid & 3,  wn   = wid >> 2;
    const int lr   = lane >> 2, lc  = lane & 3;
    const int rbase = tid >> 3;
    const int c4    = (tid & 7) * 4;

    const float* A = Ag + blockIdx.z * bA + (size_t)(blockIdx.y * 128) * lda;
    const float* B = Bg + blockIdx.z * bB + (size_t)(blockIdx.x * 128) * ldb;
    float*       C = Cg + blockIdx.z * bC + (size_t)(blockIdx.y * 128) * ldc + blockIdx.x * 128;

    float acc[2][8][4];
#pragma unroll
    for (int mi = 0; mi < 2; mi++)
#pragma unroll
        for (int nj = 0; nj < 8; nj++)
#pragma unroll
            for (int q = 0; q < 4; q++) acc[mi][nj][q] = 0.f;

    float po[4];
    if (EXPA) {
        const float* Ao = aoffg + blockIdx.z * NT + blockIdx.y * 128;
#pragma unroll
        for (int i = 0; i < 4; i++) po[i] = Ao[rbase + 32 * i];
    }

    float4 pa[4], pb[4];
#pragma unroll
    for (int i = 0; i < 4; i++) {
        pa[i] = *(const float4*)(A + (size_t)(rbase + 32 * i) * lda + c4);
        pb[i] = *(const float4*)(B + (size_t)(rbase + 32 * i) * ldb + c4);
    }

    const int NCH = K / 32;
    {
#pragma unroll
        for (int i = 0; i < 4; i++) {
            float4 va = pa[i];
            if (EXPA) {
                va.x = __expf(va.x - po[i]); va.y = __expf(va.y - po[i]);
                va.z = __expf(va.z - po[i]); va.w = __expf(va.w - po[i]);
            }
            tile_store<MODE>(SAbase, rbase + 32 * i, c4, va);
            tile_store<MODE>(SBbase, rbase + 32 * i, c4, pb[i]);
        }
    }
    __syncthreads();

    for (int c = 0; c < NCH; c++) {
        const int cur = c & 1;
        const bool more = (c + 1 < NCH);
        if (more) {
#pragma unroll
            for (int i = 0; i < 4; i++) {
                pa[i] = *(const float4*)(A + (size_t)(rbase + 32 * i) * lda + (c + 1) * 32 + c4);
                pb[i] = *(const float4*)(B + (size_t)(rbase + 32 * i) * ldb + (c + 1) * 32 + c4);
            }
        }
        const uint32_t* UA = (const uint32_t*)(SAbase + cur * TBUF);
        const uint32_t* UB = (const uint32_t*)(SBbase + cur * TBUF);
#pragma unroll
        for (int ks = 0; ks < 4; ks++) {
            const int k0 = ks * 8;
            uint32_t ah[2][4], bh[8][2];
#pragma unroll
            for (int mi = 0; mi < 2; mi++) {
                int base = (wm * 32 + mi * 16 + lr) * SROW + k0 + lc;
                ah[mi][0] = UA[base];            ah[mi][1] = UA[base + 8 * SROW];
                ah[mi][2] = UA[base + 4];        ah[mi][3] = UA[base + 8 * SROW + 4];
            }
#pragma unroll
            for (int nj = 0; nj < 8; nj++) {
                int base = (wn * 64 + nj * 8 + lr) * SROW + k0 + lc;
                bh[nj][0] = UB[base];            bh[nj][1] = UB[base + 4];
            }
#pragma unroll
            for (int mi = 0; mi < 2; mi++)
#pragma unroll
                for (int nj = 0; nj < 8; nj++)
                    mma8(acc[mi][nj], ah[mi], bh[nj]);
        }
        if (more) {
            float* SA = SAbase + (cur ^ 1) * TBUF;
            float* SB = SBbase + (cur ^ 1) * TBUF;
#pragma unroll
            for (int i = 0; i < 4; i++) {
                float4 va = pa[i];
                if (EXPA) {
                    va.x = __expf(va.x - po[i]); va.y = __expf(va.y - po[i]);
                    va.z = __expf(va.z - po[i]); va.w = __expf(va.w - po[i]);
                }
                tile_store<MODE>(SA, rbase + 32 * i, c4, va);
                tile_store<MODE>(SB, rbase + 32 * i, c4, pb[i]);
            }
        }
        __syncthreads();
    }

#pragma unroll
    for (int mi = 0; mi < 2; mi++) {
        int r = wm * 32 + mi * 16 + lr;
        float b0 = 0.f, b1 = 0.f;
        if (ACT) {
            b0 = bias[blockIdx.y * 128 + r];
            b1 = bias[blockIdx.y * 128 + r + 8];
        }
#pragma unroll
        for (int nj = 0; nj < 8; nj++) {
            int col = wn * 64 + nj * 8 + lc * 2;
            float2 v0 = make_float2(acc[mi][nj][0], acc[mi][nj][1]);
            float2 v1 = make_float2(acc[mi][nj][2], acc[mi][nj][3]);
            if (ACT) {
                v0.x = relu6f(v0.x + b0); v0.y = relu6f(v0.y + b0);
                v1.x = relu6f(v1.x + b1); v1.y = relu6f(v1.y + b1);
            }
            *(float2*)(C + (size_t)r * ldc + col)       = v0;
            *(float2*)(C + (size_t)(r + 8) * ldc + col) = v1;
        }
    }
}

// ---------------- tensor-core 1x1 conv: C = relu6(W @ X + bias) -------------------
// TRANSOUT=1 -> writes bf16 hi/lo arrays Chi/Clo as [n][ldc] (smem-staged transpose).
template<int MODE, int TRANSOUT>
__global__ __launch_bounds__(256, 1)
void conv_mma(const float* __restrict__ Wg, const float* __restrict__ Xg,
              const float* __restrict__ bias,
              const float* __restrict__ mean, const float* __restrict__ inv,
              float* __restrict__ Cg, __nv_bfloat16* __restrict__ Chig,
              __nv_bfloat16* __restrict__ Clog, int K, int ldc, size_t bC)
{
    constexpr int ABUF = 128 * SROW;
    constexpr int XBUF = 32 * 132;
    extern __shared__ float smf[];
    float* SAbase = smf;
    float* XSbase = smf + 2 * ABUF;
    float* stage  = smf;

    const int tid  = threadIdx.x;
    const int wid  = tid >> 5, lane = tid & 31;
    const int wm   = wid & 3,  wn2  = wid >> 2;
    const int lr   = lane >> 2, lc  = lane & 3;
    const int rbase = tid >> 3;
    const int c4    = (tid & 7) * 4;
    const int kk    = tid >> 5;
    const int n4    = (tid & 31) * 4;

    const int b  = blockIdx.z;
    const int n0 = blockIdx.x * 128;
    const int r0 = blockIdx.y * 128;
    const float* X = Xg + (size_t)b * K * NT;
    const float* mu = mean ? mean + b * K : nullptr;
    const float* iv = inv  ? inv  + b * K : nullptr;

    float acc[2][8][4];
#pragma unroll
    for (int mi = 0; mi < 2; mi++)
#pragma unroll
        for (int nj = 0; nj < 8; nj++)
#pragma unroll
            for (int q = 0; q < 4; q++) acc[mi][nj][q] = 0.f;

    float4 pa[4], px[4];
    float pm[4], pv[4];

    auto prefetch = [&](int c) {
#pragma unroll
        for (int i = 0; i < 4; i++)
            pa[i] = *(const float4*)(Wg + (size_t)(r0 + rbase + 32 * i) * K + c * 32 + c4);
        if (MODE == 0) {
#pragma unroll
            for (int i = 0; i < 4; i++) {
                int k = c * 32 + kk + 8 * i;
                px[i] = *(const float4*)(X + (size_t)k * NT + n0 + n4);
                pm[i] = mu ? mu[k] : 0.f;
                pv[i] = iv ? iv[k] : 1.f;
            }
        } else {
#pragma unroll
            for (int i = 0; i < 2; i++) {
                int kg = c * 32 + 2 * (kk + 8 * i);
                px[2 * i]     = *(const float4*)(X + (size_t)kg * NT + n0 + n4);
                px[2 * i + 1] = *(const float4*)(X + (size_t)(kg + 1) * NT + n0 + n4);
                pm[2 * i]     = mu ? mu[kg] : 0.f;
                pv[2 * i]     = iv ? iv[kg] : 1.f;
                pm[2 * i + 1] = mu ? mu[kg + 1] : 0.f;
                pv[2 * i + 1] = iv ? iv[kg + 1] : 1.f;
            }
        }
    };

    auto store_buf = [&](int buf) {
        float* SA  = SAbase + buf * ABUF;
        float* XS0 = XSbase + buf * XBUF;
#pragma unroll
        for (int i = 0; i < 4; i++)
            tile_store<MODE>(SA, rbase + 32 * i, c4, pa[i]);
        if (MODE == 0) {
#pragma unroll
            for (int i = 0; i < 4; i++) {
                int k = kk + 8 * i;
                float4 v = px[i];
                v.x = (v.x - pm[i]) * pv[i]; v.y = (v.y - pm[i]) * pv[i];
                v.z = (v.z - pm[i]) * pv[i]; v.w = (v.w - pm[i]) * pv[i];
                v.x = tf32rna(v.x); v.y = tf32rna(v.y);
                v.z = tf32rna(v.z); v.w = tf32rna(v.w);
                *(float4*)(XS0 + k * 132 + n4) = v;
            }
        } else {
            float* XS1 = XS0 + 16 * 132;
#pragma unroll
            for (int i = 0; i < 2; i++) {
                int kp = kk + 8 * i;
                float4 xe = px[2 * i], xo = px[2 * i + 1];
                xe.x = (xe.x - pm[2*i]) * pv[2*i]; xe.y = (xe.y - pm[2*i]) * pv[2*i];
                xe.z = (xe.z - pm[2*i]) * pv[2*i]; xe.w = (xe.w - pm[2*i]) * pv[2*i];
                xo.x = (xo.x - pm[2*i+1]) * pv[2*i+1]; xo.y = (xo.y - pm[2*i+1]) * pv[2*i+1];
                xo.z = (xo.z - pm[2*i+1]) * pv[2*i+1]; xo.w = (xo.w - pm[2*i+1]) * pv[2*i+1];
                float e[4] = {xe.x, xe.y, xe.z, xe.w};
                float o[4] = {xo.x, xo.y, xo.z, xo.w};
                uint32_t hw[4], lw[4];
#pragma unroll
                for (int j = 0; j < 4; j++) {
                    __nv_bfloat162 h = __floats2bfloat162_rn(e[j], o[j]);
                    float2 hf = __bfloat1622float2(h);
                    __nv_bfloat162 l = __floats2bfloat162_rn(e[j] - hf.x, o[j] - hf.y);
                    hw[j] = *(uint32_t*)&h;
                    lw[j] = *(uint32_t*)&l;
                }
                *(uint4*)((uint32_t*)XS0 + kp * 132 + n4) = make_uint4(hw[0], hw[1], hw[2], hw[3]);
                *(uint4*)((uint32_t*)XS1 + kp * 132 + n4) = make_uint4(lw[0], lw[1], lw[2], lw[3]);
            }
        }
    };

    const int NCH = K / 32;
    prefetch(0);
    store_buf(0);
    __syncthreads();

    for (int c = 0; c < NCH; c++) {
        const int cur = c & 1;
        const bool more = (c + 1 < NCH);
        if (more) prefetch(c + 1);

        const uint32_t* UA  = (const uint32_t*)(SAbase + cur * ABUF);
        const uint32_t* UX0 = (const uint32_t*)(XSbase + cur * XBUF);
        if (MODE == 0) {
#pragma unroll
            for (int ks = 0; ks < 4; ks++) {
                const int k0 = ks * 8;
                uint32_t ah[2][4], bh[8][2];
#pragma unroll
                for (int mi = 0; mi < 2; mi++) {
                    int base = (wm * 32 + mi * 16 + lr) * SROW + k0 + lc;
                    ah[mi][0] = UA[base];            ah[mi][1] = UA[base + 8 * SROW];
                    ah[mi][2] = UA[base + 4];        ah[mi][3] = UA[base + 8 * SROW + 4];
                }
#pragma unroll
                for (int nj = 0; nj < 8; nj++) {
                    int col = wn2 * 64 + nj * 8 + lr;
                    bh[nj][0] = UX0[(k0 + lc) * 132 + col];
                    bh[nj][1] = UX0[(k0 + lc + 4) * 132 + col];
                }
#pragma unroll
                for (int mi = 0; mi < 2; mi++)
#pragma unroll
                    for (int nj = 0; nj < 8; nj++)
                        mma8(acc[mi][nj], ah[mi], bh[nj]);
            }
        } else {
            const uint32_t* UX1 = UX0 + 16 * 132;
#pragma unroll
            for (int s = 0; s < 2; s++) {
                const int k0 = s * 8;
                uint32_t ah[2][4], al[2][4], bh[8][2], bl[8][2];
#pragma unroll
                for (int mi = 0; mi < 2; mi++) {
                    int base = (wm * 32 + mi * 16 + lr) * SROW + k0 + lc;
                    ah[mi][0] = UA[base];            ah[mi][1] = UA[base + 8 * SROW];
                    ah[mi][2] = UA[base + 4];        ah[mi][3] = UA[base + 8 * SROW + 4];
                    al[mi][0] = UA[base + 16];       al[mi][1] = UA[base + 8 * SROW + 16];
                    al[mi][2] = UA[base + 20];       al[mi][3] = UA[base + 8 * SROW + 20];
                }
#pragma unroll
                for (int nj = 0; nj < 8; nj++) {
                    int col = wn2 * 64 + nj * 8 + lr;
                    bh[nj][0] = UX0[(k0 + lc) * 132 + col];
                    bh[nj][1] = UX0[(k0 + lc + 4) * 132 + col];
                    bl[nj][0] = UX1[(k0 + lc) * 132 + col];
                    bl[nj][1] = UX1[(k0 + lc + 4) * 132 + col];
                }
#pragma unroll
                for (int mi = 0; mi < 2; mi++)
#pragma unroll
                    for (int nj = 0; nj < 8; nj++) {
                        mma16(acc[mi][nj], ah[mi], bh[nj]);
                        mma16(acc[mi][nj], ah[mi], bl[nj]);
                        mma16(acc[mi][nj], al[mi], bh[nj]);
                    }
            }
        }
        if (more) store_buf(cur ^ 1);
        __syncthreads();
    }

    if (!TRANSOUT) {
        float* C = Cg + b * bC;
#pragma unroll
        for (int mi = 0; mi < 2; mi++) {
            int r = wm * 32 + mi * 16 + lr;
            float b0 = bias[r0 + r], b1 = bias[r0 + r + 8];
#pragma unroll
            for (int nj = 0; nj < 8; nj++) {
                int col = wn2 * 64 + nj * 8 + lc * 2;
                float2 v0 = make_float2(relu6f(acc[mi][nj][0] + b0),
                                        relu6f(acc[mi][nj][1] + b0));
                float2 v1 = make_float2(relu6f(acc[mi][nj][2] + b1),
                                        relu6f(acc[mi][nj][3] + b1));
                *(float2*)(C + (size_t)(r0 + r) * ldc + n0 + col)     = v0;
                *(float2*)(C + (size_t)(r0 + r + 8) * ldc + n0 + col) = v1;
            }
        }
    } else {
        __nv_bfloat16* Chi = Chig + (size_t)b * NT * ldc;
        __nv_bfloat16* Clo = Clog + (size_t)b * NT * ldc;
#pragma unroll
        for (int mi = 0; mi < 2; mi++) {
            int r = wm * 32 + mi * 16 + lr;
            float b0 = bias[r0 + r], b1 = bias[r0 + r + 8];
#pragma unroll
            for (int nj = 0; nj < 8; nj++) {
                int nl = wn2 * 64 + nj * 8 + lc * 2;
                stage[(size_t)nl * 132 + r]           = relu6f(acc[mi][nj][0] + b0);
                stage[(size_t)(nl + 1) * 132 + r]     = relu6f(acc[mi][nj][1] + b0);
                stage[(size_t)nl * 132 + r + 8]       = relu6f(acc[mi][nj][2] + b1);
                stage[(size_t)(nl + 1) * 132 + r + 8] = relu6f(acc[mi][nj][3] + b1);
            }
        }
        __syncthreads();
#pragma unroll
        for (int i = 0; i < 16; i++) {
            int e = tid + i * 256;
            int n = e >> 5, r4 = (e & 31) * 4;
            float4 v = *(const float4*)(stage + n * 132 + r4);
            __nv_bfloat162 h0 = __floats2bfloat162_rn(v.x, v.y);
            __nv_bfloat162 h1 = __floats2bfloat162_rn(v.z, v.w);
            float2 f0 = __bfloat1622float2(h0);
            float2 f1 = __bfloat1622float2(h1);
            __nv_bfloat162 l0 = __floats2bfloat162_rn(v.x - f0.x, v.y - f0.y);
            __nv_bfloat162 l1 = __floats2bfloat162_rn(v.z - f1.x, v.w - f1.y);
            size_t off = (size_t)(n0 + n) * ldc + r0 + r4;
            *(uint2*)(Chi + off) = make_uint2(*(uint32_t*)&h0, *(uint32_t*)&h1);
            *(uint2*)(Clo + off) = make_uint2(*(uint32_t*)&l0, *(uint32_t*)&l1);
        }
    }
}

// ---------------- row stats for softmax: off[row] = max + ln(sum exp) ------------
__global__ __launch_bounds__(256) void rowstat_kernel(const float* __restrict__ S,
                                                      float* __restrict__ off) {
    const float* p = S + (size_t)blockIdx.x * NT;
    int tid = threadIdx.x;
    float4 v[4];
    float mx = -1e30f;
#pragma unroll
    for (int i = 0; i < 4; i++) {
        v[i] = ((const float4*)p)[tid + i * 256];
        mx = fmaxf(mx, fmaxf(fmaxf(v[i].x, v[i].y), fmaxf(v[i].z, v[i].w)));
    }
    __shared__ float redm[8], reds[8];
#pragma unroll
    for (int o = 16; o; o >>= 1) mx = fmaxf(mx, __shfl_xor_sync(0xffffffffu, mx, o));
    if ((tid & 31) == 0) redm[tid >> 5] = mx;
    __syncthreads();
    mx = fmaxf(fmaxf(fmaxf(redm[0], redm[1]), fmaxf(redm[2], redm[3])),
               fmaxf(fmaxf(redm[4], redm[5]), fmaxf(redm[6], redm[7])));
    float s = 0.f;
#pragma unroll
    for (int i = 0; i < 4; i++) {
        s += __expf(v[i].x - mx) + __expf(v[i].y - mx)
           + __expf(v[i].z - mx) + __expf(v[i].w - mx);
    }
#pragma unroll
    for (int o = 16; o; o >>= 1) s += __shfl_xor_sync(0xffffffffu, s, o);
    if ((tid & 31) == 0) reds[tid >> 5] = s;
    __syncthreads();
    if (tid == 0) {
        s = reds[0] + reds[1] + reds[2] + reds[3] + reds[4] + reds[5] + reds[6] + reds[7];
        off[blockIdx.x] = mx + logf(s);
    }
}

// ---------------- launch ----------------
extern "C" void kernel_launch(void* const* d_in, const int* in_sizes, int n_in,
                              void* d_out, int out_size) {
    const float* Fc    = (const float*)d_in[0];
    const float* Fs    = (const float*)d_in[1];
    const float* f_w   = (const float*)d_in[2];
    const float* f_b   = (const float*)d_in[3];
    const float* g_w   = (const float*)d_in[4];
    const float* g_b   = (const float*)d_in[5];
    const float* h_w   = (const float*)d_in[6];
    const float* h_b   = (const float*)d_in[7];
    const float* out_w = (const float*)d_in[8];
    const float* out_b = (const float*)d_in[9];
    float* out = (float*)d_out;

    float *ph, *pfcs, *pS, *psoff, *pmean, *pinv;
    __nv_bfloat16 *pfhi, *pflo, *pghi, *pglo;
    cudaGetSymbolAddress((void**)&pfhi,  d_fThi);
    cudaGetSymbolAddress((void**)&pflo,  d_fTlo);
    cudaGetSymbolAddress((void**)&pghi,  d_gThi);
    cudaGetSymbolAddress((void**)&pglo,  d_gTlo);
    cudaGetSymbolAddress((void**)&ph,    d_h);
    cudaGetSymbolAddress((void**)&pfcs,  d_fcs);
    cudaGetSymbolAddress((void**)&pS,    d_S);
    cudaGetSymbolAddress((void**)&psoff, d_soff);
    cudaGetSymbolAddress((void**)&pmean, d_mean);
    cudaGetSymbolAddress((void**)&pinv,  d_inv);

    const int SM_G  = 4 * 128 * SROW * 4;                   // 73728 (mma_gemm, 2-stage)
    const int SM_S  = 4 * 2 * 128 * SROW * 4;               // 147456 (attn_sgemm, 4-stage)
    const int SM_C  = (2 * 128 * SROW + 2 * 32 * 132) * 4;  // 70656 (conv)
    cudaFuncSetAttribute(attn_sgemm,        cudaFuncAttributeMaxDynamicSharedMemorySize, SM_S);
    cudaFuncSetAttribute(mma_gemm<0, 0, 1>, cudaFuncAttributeMaxDynamicSharedMemorySize, SM_G);
    cudaFuncSetAttribute(mma_gemm<0, 1, 0>, cudaFuncAttributeMaxDynamicSharedMemorySize, SM_G);
    cudaFuncSetAttribute(conv_mma<1, 1>,    cudaFuncAttributeMaxDynamicSharedMemorySize, SM_C);
    cudaFuncSetAttribute(conv_mma<0, 0>,    cudaFuncAttributeMaxDynamicSharedMemorySize, SM_C);

    stats_kernel<<<dim3(BATCH * CIN, 2), 256>>>(Fc, Fs);

    // fT = relu6(f_w @ mvn(Fc) + f_b)^T  -> bf16 hi/lo [n][d]
    conv_mma<1, 1><<<dim3(NT / 128, CH / 128, BATCH), 256, SM_C>>>(
        f_w, Fc, f_b, pmean, pinv, nullptr, pfhi, pflo, CIN, CH, 0);
    // gT = relu6(g_w @ mvn(Fs) + g_b)^T  -> bf16 hi/lo [m][d]
    conv_mma<1, 1><<<dim3(NT / 128, CH / 128, BATCH), 256, SM_C>>>(
        g_w, Fs, g_b, pmean + BATCH * CIN, pinv + BATCH * CIN, nullptr, pghi, pglo, CIN, CH, 0);
    // h[d][m] = relu6(h_w @ Fs + h_b)    (1xtf32, fp32 out)
    conv_mma<0, 0><<<dim3(NT / 128, CH / 128, BATCH), 256, SM_C>>>(
        h_w, Fs, h_b, nullptr, nullptr, ph, nullptr, nullptr, CIN, NT, (size_t)CH * NT);

    // S[n][m] = fT . gT^T   (bf16 split, cp.async 4-stage)
    attn_sgemm<<<dim3(NT / 128, NT / 128, BATCH), 256, SM_S>>>(pfhi, pflo, pghi, pglo, pS);

    // per-row max + ln(sum exp)
    rowstat_kernel<<<BATCH * NT, 256>>>(pS, psoff);

    // fcs[n][d] = softmax(S) . h^T   (1xtf32, exp at A-tile store)
    mma_gemm<0, 0, 1><<<dim3(CH / 128, NT / 128, BATCH), 256, SM_G>>>(
        pS, ph, nullptr, psoff, pfcs, NT, NT, NT, CH,
        (size_t)NT * NT, (size_t)CH * NT, (size_t)NT * CH);

    // out[r][n] = relu6(out_w @ fcs^T + out_b)  (1xtf32)
    mma_gemm<0, 1, 0><<<dim3(NT / 128, CIN / 128, BATCH), 256, SM_G>>>(
        out_w, pfcs, out_b, nullptr, out, CH, CH, CH, NT,
        (size_t)0, (size_t)NT * CH, (size_t)CIN * NT);
}

// round 17
// speedup vs baseline: 1.0491x; 1.0491x over previous
#include <cuda_runtime.h>
#include <cuda_bf16.h>
#include <cstdint>
#include <cstddef>

#define NT    4096      // H*W tokens
#define CH    256       // hidden channels
#define CIN   512       // input channels
#define BATCH 4
#define SROW  36        // smem row stride (words), ≡4 mod 32 -> conflict-free fragments

// ---------------- scratch (device globals; no allocation in kernel_launch) --------
__device__ float d_fT [(size_t)BATCH * NT * CH];   // fT [b][n][d]
__device__ float d_gT [(size_t)BATCH * NT * CH];   // gT [b][m][d]
__device__ float d_h  [(size_t)BATCH * CH * NT];   // h  [b][d][m]
__device__ float d_fcs[(size_t)BATCH * NT * CH];   // Fcs[b][n][d]
__device__ float d_S  [(size_t)BATCH * NT * NT];   // scores [b][n][m]
__device__ float d_soff[(size_t)BATCH * NT];       // per-row max + ln(sum)
__device__ float d_mean[2 * BATCH * CIN];
__device__ float d_inv [2 * BATCH * CIN];

__device__ __forceinline__ float relu6f(float x) { return fminf(fmaxf(x, 0.0f), 6.0f); }
__device__ __forceinline__ float tf32rna(float x) {
    float r; asm("cvt.rna.tf32.f32 %0, %1;" : "=f"(r) : "f"(x)); return r;
}
// m16n8k8 tf32 MMA (baseline PTX, sm_80+)
__device__ __forceinline__ void mma8(float* d, const uint32_t* a, const uint32_t* b) {
    asm volatile("mma.sync.aligned.m16n8k8.row.col.f32.tf32.tf32.f32 "
                 "{%0,%1,%2,%3},{%4,%5,%6,%7},{%8,%9},{%0,%1,%2,%3};"
                 : "+f"(d[0]), "+f"(d[1]), "+f"(d[2]), "+f"(d[3])
                 : "r"(a[0]), "r"(a[1]), "r"(a[2]), "r"(a[3]), "r"(b[0]), "r"(b[1]));
}
// m16n8k16 bf16 MMA (baseline PTX, sm_80+)
__device__ __forceinline__ void mma16(float* d, const uint32_t* a, const uint32_t* b) {
    asm volatile("mma.sync.aligned.m16n8k16.row.col.f32.bf16.bf16.f32 "
                 "{%0,%1,%2,%3},{%4,%5,%6,%7},{%8,%9},{%0,%1,%2,%3};"
                 : "+f"(d[0]), "+f"(d[1]), "+f"(d[2]), "+f"(d[3])
                 : "r"(a[0]), "r"(a[1]), "r"(a[2]), "r"(a[3]), "r"(b[0]), "r"(b[1]));
}

// Store 4 consecutive k floats of one tile row into smem.
// MODE 0: tf32-rounded floats at word col c4. MODE 1: bf16 hi/lo pairs (hi @c4/2, lo @+16).
template<int MODE>
__device__ __forceinline__ void tile_store(float* S, int r, int c4, float4 v) {
    if (MODE == 0) {
        v.x = tf32rna(v.x); v.y = tf32rna(v.y);
        v.z = tf32rna(v.z); v.w = tf32rna(v.w);
        *(float4*)(S + r * SROW + c4) = v;
    } else {
        __nv_bfloat162 h0 = __floats2bfloat162_rn(v.x, v.y);
        __nv_bfloat162 h1 = __floats2bfloat162_rn(v.z, v.w);
        float2 f0 = __bfloat1622float2(h0);
        float2 f1 = __bfloat1622float2(h1);
        __nv_bfloat162 l0 = __floats2bfloat162_rn(v.x - f0.x, v.y - f0.y);
        __nv_bfloat162 l1 = __floats2bfloat162_rn(v.z - f1.x, v.w - f1.y);
        uint32_t* W = (uint32_t*)(S + r * SROW) + (c4 >> 1);
        *(uint2*)(W)      = make_uint2(*(uint32_t*)&h0, *(uint32_t*)&h1);
        *(uint2*)(W + 16) = make_uint2(*(uint32_t*)&l0, *(uint32_t*)&l1);
    }
}

// ---------------- per-(b,c) instance-norm stats, ddof=1 ----------------
__global__ __launch_bounds__(256) void stats_kernel(const float* __restrict__ Fc,
                                                    const float* __restrict__ Fs) {
    int inst  = blockIdx.x;
    int which = blockIdx.y;
    const float* src = (which ? Fs : Fc) + (size_t)inst * NT;
    int tid = threadIdx.x;
    float s = 0.f, ss = 0.f;
    for (int e = tid; e < NT / 4; e += 256) {
        float4 v = ((const float4*)src)[e];
        s  += v.x + v.y + v.z + v.w;
        ss += v.x * v.x + v.y * v.y + v.z * v.z + v.w * v.w;
    }
    for (int o = 16; o; o >>= 1) {
        s  += __shfl_xor_sync(0xffffffffu, s, o);
        ss += __shfl_xor_sync(0xffffffffu, ss, o);
    }
    __shared__ float sb[8], ssb[8];
    if ((tid & 31) == 0) { sb[tid >> 5] = s; ssb[tid >> 5] = ss; }
    __syncthreads();
    if (tid == 0) {
        s = 0.f; ss = 0.f;
        for (int w = 0; w < 8; w++) { s += sb[w]; ss += ssb[w]; }
        float mean = s / (float)NT;
        float var  = (ss - s * mean) / (float)(NT - 1);
        d_mean[which * BATCH * CIN + inst] = mean;
        d_inv [which * BATCH * CIN + inst] = rsqrtf(var + 1e-5f);
    }
}

// ---------------- MMA GEMM: C[M,N] = A[M,K] * B[N,K]^T ---------------------------
// CTA tile 128x128, K-chunk 32, 16 warps (32x32 warp tile), 512 threads, dbl-buffer.
// MODE 0: single tf32. MODE 1: 2-way split bf16 (hi/lo, 3 products).
// EXPA: A -> exp(a - aoff[row]) at smem-store time (MODE0 only).
template<int MODE, int ACT, int EXPA>
__global__ __launch_bounds__(512, 1)
void mma_gemm(const float* __restrict__ Ag, const float* __restrict__ Bg,
              const float* __restrict__ bias, const float* __restrict__ aoffg,
              float* __restrict__ Cg,
              int K, int lda, int ldb, int ldc,
              size_t bA, size_t bB, size_t bC)
{
    constexpr int TBUF = 128 * SROW;
    extern __shared__ float smf[];
    float* SAbase = smf;                 // 2 x TBUF
    float* SBbase = smf + 2 * TBUF;      // 2 x TBUF

    const int tid  = threadIdx.x;
    const int wid  = tid >> 5, lane = tid & 31;
    const int wm   = wid & 3,  wn   = wid >> 2;   // 4 x 4 warp grid
    const int lr   = lane >> 2, lc  = lane & 3;
    const int rbase = tid >> 2;                   // 0..127 (one tile row per thread)
    const int cc    = (tid & 3) * 8;              // 8 floats per thread

    const float* A = Ag + blockIdx.z * bA + (size_t)(blockIdx.y * 128) * lda;
    const float* B = Bg + blockIdx.z * bB + (size_t)(blockIdx.x * 128) * ldb;
    float*       C = Cg + blockIdx.z * bC + (size_t)(blockIdx.y * 128) * ldc + blockIdx.x * 128;

    float acc[2][4][4];
#pragma unroll
    for (int mi = 0; mi < 2; mi++)
#pragma unroll
        for (int nj = 0; nj < 4; nj++)
#pragma unroll
            for (int q = 0; q < 4; q++) acc[mi][nj][q] = 0.f;

    float po = 0.f;
    if (EXPA) po = aoffg[blockIdx.z * NT + blockIdx.y * 128 + rbase];

    float4 pa0, pa1, pb0, pb1;
    auto ld = [&](int c) {
        const float* ap = A + (size_t)rbase * lda + c * 32 + cc;
        const float* bp = B + (size_t)rbase * ldb + c * 32 + cc;
        pa0 = *(const float4*)(ap);
        pa1 = *(const float4*)(ap + 4);
        pb0 = *(const float4*)(bp);
        pb1 = *(const float4*)(bp + 4);
    };
    auto st = [&](float* SA, float* SB) {
        float4 va0 = pa0, va1 = pa1;
        if (EXPA) {
            va0.x = __expf(va0.x - po); va0.y = __expf(va0.y - po);
            va0.z = __expf(va0.z - po); va0.w = __expf(va0.w - po);
            va1.x = __expf(va1.x - po); va1.y = __expf(va1.y - po);
            va1.z = __expf(va1.z - po); va1.w = __expf(va1.w - po);
        }
        tile_store<MODE>(SA, rbase, cc,     va0);
        tile_store<MODE>(SA, rbase, cc + 4, va1);
        tile_store<MODE>(SB, rbase, cc,     pb0);
        tile_store<MODE>(SB, rbase, cc + 4, pb1);
    };

    const int NCH = K / 32;
    ld(0);
    st(SAbase, SBbase);
    __syncthreads();

    for (int c = 0; c < NCH; c++) {
        const int cur = c & 1;
        const bool more = (c + 1 < NCH);
        if (more) ld(c + 1);

        const uint32_t* UA = (const uint32_t*)(SAbase + cur * TBUF);
        const uint32_t* UB = (const uint32_t*)(SBbase + cur * TBUF);
        if (MODE == 0) {
#pragma unroll
            for (int ks = 0; ks < 4; ks++) {
                const int k0 = ks * 8;
                uint32_t ah[2][4], bh[4][2];
#pragma unroll
                for (int mi = 0; mi < 2; mi++) {
                    int base = (wm * 32 + mi * 16 + lr) * SROW + k0 + lc;
                    ah[mi][0] = UA[base];            ah[mi][1] = UA[base + 8 * SROW];
                    ah[mi][2] = UA[base + 4];        ah[mi][3] = UA[base + 8 * SROW + 4];
                }
#pragma unroll
                for (int nj = 0; nj < 4; nj++) {
                    int base = (wn * 32 + nj * 8 + lr) * SROW + k0 + lc;
                    bh[nj][0] = UB[base];            bh[nj][1] = UB[base + 4];
                }
#pragma unroll
                for (int mi = 0; mi < 2; mi++)
#pragma unroll
                    for (int nj = 0; nj < 4; nj++)
                        mma8(acc[mi][nj], ah[mi], bh[nj]);
            }
        } else {
#pragma unroll
            for (int s = 0; s < 2; s++) {
                const int k0 = s * 8;
                uint32_t ah[2][4], al[2][4], bh[4][2], bl[4][2];
#pragma unroll
                for (int mi = 0; mi < 2; mi++) {
                    int base = (wm * 32 + mi * 16 + lr) * SROW + k0 + lc;
                    ah[mi][0] = UA[base];            ah[mi][1] = UA[base + 8 * SROW];
                    ah[mi][2] = UA[base + 4];        ah[mi][3] = UA[base + 8 * SROW + 4];
                    al[mi][0] = UA[base + 16];       al[mi][1] = UA[base + 8 * SROW + 16];
                    al[mi][2] = UA[base + 20];       al[mi][3] = UA[base + 8 * SROW + 20];
                }
#pragma unroll
                for (int nj = 0; nj < 4; nj++) {
                    int base = (wn * 32 + nj * 8 + lr) * SROW + k0 + lc;
                    bh[nj][0] = UB[base];            bh[nj][1] = UB[base + 4];
                    bl[nj][0] = UB[base + 16];       bl[nj][1] = UB[base + 20];
                }
#pragma unroll
                for (int mi = 0; mi < 2; mi++)
#pragma unroll
                    for (int nj = 0; nj < 4; nj++) {
                        mma16(acc[mi][nj], ah[mi], bh[nj]);
                        mma16(acc[mi][nj], ah[mi], bl[nj]);
                        mma16(acc[mi][nj], al[mi], bh[nj]);
                    }
            }
        }
        if (more) st(SAbase + (cur ^ 1) * TBUF, SBbase + (cur ^ 1) * TBUF);
        __syncthreads();
    }

#pragma unroll
    for (int mi = 0; mi < 2; mi++) {
        int r = wm * 32 + mi * 16 + lr;
        float b0 = 0.f, b1 = 0.f;
        if (ACT) {
            b0 = bias[blockIdx.y * 128 + r];
            b1 = bias[blockIdx.y * 128 + r + 8];
        }
#pragma unroll
        for (int nj = 0; nj < 4; nj++) {
            int col = wn * 32 + nj * 8 + lc * 2;
            float2 v0 = make_float2(acc[mi][nj][0], acc[mi][nj][1]);
            float2 v1 = make_float2(acc[mi][nj][2], acc[mi][nj][3]);
            if (ACT) {
                v0.x = relu6f(v0.x + b0); v0.y = relu6f(v0.y + b0);
                v1.x = relu6f(v1.x + b1); v1.y = relu6f(v1.y + b1);
            }
            *(float2*)(C + (size_t)r * ldc + col)       = v0;
            *(float2*)(C + (size_t)(r + 8) * ldc + col) = v1;
        }
    }
}

// ---------------- tensor-core 1x1 conv: C = relu6(W @ X + bias) — R14 version ----
template<int MODE, int TRANSOUT>
__global__ __launch_bounds__(256, 1)
void conv_mma(const float* __restrict__ Wg, const float* __restrict__ Xg,
              const float* __restrict__ bias,
              const float* __restrict__ mean, const float* __restrict__ inv,
              float* __restrict__ Cg, int K, int ldc, size_t bC)
{
    constexpr int ABUF = 128 * SROW;
    constexpr int XBUF = 32 * 132;
    extern __shared__ float smf[];
    float* SAbase = smf;
    float* XSbase = smf + 2 * ABUF;
    float* stage  = smf;

    const int tid  = threadIdx.x;
    const int wid  = tid >> 5, lane = tid & 31;
    const int wm   = wid & 3,  wn2  = wid >> 2;
    const int lr   = lane >> 2, lc  = lane & 3;
    const int rbase = tid >> 3;
    const int c4    = (tid & 7) * 4;
    const int kk    = tid >> 5;
    const int n4    = (tid & 31) * 4;

    const int b  = blockIdx.z;
    const int n0 = blockIdx.x * 128;
    const int r0 = blockIdx.y * 128;
    const float* X = Xg + (size_t)b * K * NT;
    const float* mu = mean ? mean + b * K : nullptr;
    const float* iv = inv  ? inv  + b * K : nullptr;
    float* C = Cg + b * bC;

    float acc[2][8][4];
#pragma unroll
    for (int mi = 0; mi < 2; mi++)
#pragma unroll
        for (int nj = 0; nj < 8; nj++)
#pragma unroll
            for (int q = 0; q < 4; q++) acc[mi][nj][q] = 0.f;

    float4 pa[4], px[4];
    float pm[4], pv[4];

    auto prefetch = [&](int c) {
#pragma unroll
        for (int i = 0; i < 4; i++)
            pa[i] = *(const float4*)(Wg + (size_t)(r0 + rbase + 32 * i) * K + c * 32 + c4);
        if (MODE == 0) {
#pragma unroll
            for (int i = 0; i < 4; i++) {
                int k = c * 32 + kk + 8 * i;
                px[i] = *(const float4*)(X + (size_t)k * NT + n0 + n4);
                pm[i] = mu ? mu[k] : 0.f;
                pv[i] = iv ? iv[k] : 1.f;
            }
        } else {
#pragma unroll
            for (int i = 0; i < 2; i++) {
                int kg = c * 32 + 2 * (kk + 8 * i);
                px[2 * i]     = *(const float4*)(X + (size_t)kg * NT + n0 + n4);
                px[2 * i + 1] = *(const float4*)(X + (size_t)(kg + 1) * NT + n0 + n4);
                pm[2 * i]     = mu ? mu[kg] : 0.f;
                pv[2 * i]     = iv ? iv[kg] : 1.f;
                pm[2 * i + 1] = mu ? mu[kg + 1] : 0.f;
                pv[2 * i + 1] = iv ? iv[kg + 1] : 1.f;
            }
        }
    };

    auto store_buf = [&](int buf) {
        float* SA  = SAbase + buf * ABUF;
        float* XS0 = XSbase + buf * XBUF;
#pragma unroll
        for (int i = 0; i < 4; i++)
            tile_store<MODE>(SA, rbase + 32 * i, c4, pa[i]);
        if (MODE == 0) {
#pragma unroll
            for (int i = 0; i < 4; i++) {
                int k = kk + 8 * i;
                float4 v = px[i];
                v.x = (v.x - pm[i]) * pv[i]; v.y = (v.y - pm[i]) * pv[i];
                v.z = (v.z - pm[i]) * pv[i]; v.w = (v.w - pm[i]) * pv[i];
                v.x = tf32rna(v.x); v.y = tf32rna(v.y);
                v.z = tf32rna(v.z); v.w = tf32rna(v.w);
                *(float4*)(XS0 + k * 132 + n4) = v;
            }
        } else {
            float* XS1 = XS0 + 16 * 132;
#pragma unroll
            for (int i = 0; i < 2; i++) {
                int kp = kk + 8 * i;
                float4 xe = px[2 * i], xo = px[2 * i + 1];
                xe.x = (xe.x - pm[2*i]) * pv[2*i]; xe.y = (xe.y - pm[2*i]) * pv[2*i];
                xe.z = (xe.z - pm[2*i]) * pv[2*i]; xe.w = (xe.w - pm[2*i]) * pv[2*i];
                xo.x = (xo.x - pm[2*i+1]) * pv[2*i+1]; xo.y = (xo.y - pm[2*i+1]) * pv[2*i+1];
                xo.z = (xo.z - pm[2*i+1]) * pv[2*i+1]; xo.w = (xo.w - pm[2*i+1]) * pv[2*i+1];
                float e[4] = {xe.x, xe.y, xe.z, xe.w};
                float o[4] = {xo.x, xo.y, xo.z, xo.w};
                uint32_t hw[4], lw[4];
#pragma unroll
                for (int j = 0; j < 4; j++) {
                    __nv_bfloat162 h = __floats2bfloat162_rn(e[j], o[j]);
                    float2 hf = __bfloat1622float2(h);
                    __nv_bfloat162 l = __floats2bfloat162_rn(e[j] - hf.x, o[j] - hf.y);
                    hw[j] = *(uint32_t*)&h;
                    lw[j] = *(uint32_t*)&l;
                }
                *(uint4*)((uint32_t*)XS0 + kp * 132 + n4) = make_uint4(hw[0], hw[1], hw[2], hw[3]);
                *(uint4*)((uint32_t*)XS1 + kp * 132 + n4) = make_uint4(lw[0], lw[1], lw[2], lw[3]);
            }
        }
    };

    const int NCH = K / 32;
    prefetch(0);
    store_buf(0);
    __syncthreads();

    for (int c = 0; c < NCH; c++) {
        const int cur = c & 1;
        const bool more = (c + 1 < NCH);
        if (more) prefetch(c + 1);

        const uint32_t* UA  = (const uint32_t*)(SAbase + cur * ABUF);
        const uint32_t* UX0 = (const uint32_t*)(XSbase + cur * XBUF);
        if (MODE == 0) {
#pragma unroll
            for (int ks = 0; ks < 4; ks++) {
                const int k0 = ks * 8;
                uint32_t ah[2][4], bh[8][2];
#pragma unroll
                for (int mi = 0; mi < 2; mi++) {
                    int base = (wm * 32 + mi * 16 + lr) * SROW + k0 + lc;
                    ah[mi][0] = UA[base];            ah[mi][1] = UA[base + 8 * SROW];
                    ah[mi][2] = UA[base + 4];        ah[mi][3] = UA[base + 8 * SROW + 4];
                }
#pragma unroll
                for (int nj = 0; nj < 8; nj++) {
                    int col = wn2 * 64 + nj * 8 + lr;
                    bh[nj][0] = UX0[(k0 + lc) * 132 + col];
                    bh[nj][1] = UX0[(k0 + lc + 4) * 132 + col];
                }
#pragma unroll
                for (int mi = 0; mi < 2; mi++)
#pragma unroll
                    for (int nj = 0; nj < 8; nj++)
                        mma8(acc[mi][nj], ah[mi], bh[nj]);
            }
        } else {
            const uint32_t* UX1 = UX0 + 16 * 132;
#pragma unroll
            for (int s = 0; s < 2; s++) {
                const int k0 = s * 8;
                uint32_t ah[2][4], al[2][4], bh[8][2], bl[8][2];
#pragma unroll
                for (int mi = 0; mi < 2; mi++) {
                    int base = (wm * 32 + mi * 16 + lr) * SROW + k0 + lc;
                    ah[mi][0] = UA[base];            ah[mi][1] = UA[base + 8 * SROW];
                    ah[mi][2] = UA[base + 4];        ah[mi][3] = UA[base + 8 * SROW + 4];
                    al[mi][0] = UA[base + 16];       al[mi][1] = UA[base + 8 * SROW + 16];
                    al[mi][2] = UA[base + 20];       al[mi][3] = UA[base + 8 * SROW + 20];
                }
#pragma unroll
                for (int nj = 0; nj < 8; nj++) {
                    int col = wn2 * 64 + nj * 8 + lr;
                    bh[nj][0] = UX0[(k0 + lc) * 132 + col];
                    bh[nj][1] = UX0[(k0 + lc + 4) * 132 + col];
                    bl[nj][0] = UX1[(k0 + lc) * 132 + col];
                    bl[nj][1] = UX1[(k0 + lc + 4) * 132 + col];
                }
#pragma unroll
                for (int mi = 0; mi < 2; mi++)
#pragma unroll
                    for (int nj = 0; nj < 8; nj++) {
                        mma16(acc[mi][nj], ah[mi], bh[nj]);
                        mma16(acc[mi][nj], ah[mi], bl[nj]);
                        mma16(acc[mi][nj], al[mi], bh[nj]);
                    }
            }
        }
        if (more) store_buf(cur ^ 1);
        __syncthreads();
    }

    if (!TRANSOUT) {
#pragma unroll
        for (int mi = 0; mi < 2; mi++) {
            int r = wm * 32 + mi * 16 + lr;
            float b0 = bias[r0 + r], b1 = bias[r0 + r + 8];
#pragma unroll
            for (int nj = 0; nj < 8; nj++) {
                int col = wn2 * 64 + nj * 8 + lc * 2;
                float2 v0 = make_float2(relu6f(acc[mi][nj][0] + b0),
                                        relu6f(acc[mi][nj][1] + b0));
                float2 v1 = make_float2(relu6f(acc[mi][nj][2] + b1),
                                        relu6f(acc[mi][nj][3] + b1));
                *(float2*)(C + (size_t)(r0 + r) * ldc + n0 + col)     = v0;
                *(float2*)(C + (size_t)(r0 + r + 8) * ldc + n0 + col) = v1;
            }
        }
    } else {
#pragma unroll
        for (int mi = 0; mi < 2; mi++) {
            int r = wm * 32 + mi * 16 + lr;
            float b0 = bias[r0 + r], b1 = bias[r0 + r + 8];
#pragma unroll
            for (int nj = 0; nj < 8; nj++) {
                int nl = wn2 * 64 + nj * 8 + lc * 2;
                stage[(size_t)nl * 132 + r]           = relu6f(acc[mi][nj][0] + b0);
                stage[(size_t)(nl + 1) * 132 + r]     = relu6f(acc[mi][nj][1] + b0);
                stage[(size_t)nl * 132 + r + 8]       = relu6f(acc[mi][nj][2] + b1);
                stage[(size_t)(nl + 1) * 132 + r + 8] = relu6f(acc[mi][nj][3] + b1);
            }
        }
        __syncthreads();
#pragma unroll
        for (int i = 0; i < 16; i++) {
            int e = tid + i * 256;
            int n = e >> 5, r4 = (e & 31) * 4;
            *(float4*)(C + (size_t)(n0 + n) * ldc + r0 + r4) = *(const float4*)(stage + n * 132 + r4);
        }
    }
}

// ---------------- row stats for softmax: off[row] = max + ln(sum exp) ------------
__global__ __launch_bounds__(256) void rowstat_kernel(const float* __restrict__ S,
                                                      float* __restrict__ off) {
    const float* p = S + (size_t)blockIdx.x * NT;
    int tid = threadIdx.x;
    float4 v[4];
    float mx = -1e30f;
#pragma unroll
    for (int i = 0; i < 4; i++) {
        v[i] = ((const float4*)p)[tid + i * 256];
        mx = fmaxf(mx, fmaxf(fmaxf(v[i].x, v[i].y), fmaxf(v[i].z, v[i].w)));
    }
    __shared__ float redm[8], reds[8];
#pragma unroll
    for (int o = 16; o; o >>= 1) mx = fmaxf(mx, __shfl_xor_sync(0xffffffffu, mx, o));
    if ((tid & 31) == 0) redm[tid >> 5] = mx;
    __syncthreads();
    mx = fmaxf(fmaxf(fmaxf(redm[0], redm[1]), fmaxf(redm[2], redm[3])),
               fmaxf(fmaxf(redm[4], redm[5]), fmaxf(redm[6], redm[7])));
    float s = 0.f;
#pragma unroll
    for (int i = 0; i < 4; i++) {
        s += __expf(v[i].x - mx) + __expf(v[i].y - mx)
           + __expf(v[i].z - mx) + __expf(v[i].w - mx);
    }
#pragma unroll
    for (int o = 16; o; o >>= 1) s += __shfl_xor_sync(0xffffffffu, s, o);
    if ((tid & 31) == 0) reds[tid >> 5] = s;
    __syncthreads();
    if (tid == 0) {
        s = reds[0] + reds[1] + reds[2] + reds[3] + reds[4] + reds[5] + reds[6] + reds[7];
        off[blockIdx.x] = mx + logf(s);
    }
}

// ---------------- launch ----------------
extern "C" void kernel_launch(void* const* d_in, const int* in_sizes, int n_in,
                              void* d_out, int out_size) {
    const float* Fc    = (const float*)d_in[0];
    const float* Fs    = (const float*)d_in[1];
    const float* f_w   = (const float*)d_in[2];
    const float* f_b   = (const float*)d_in[3];
    const float* g_w   = (const float*)d_in[4];
    const float* g_b   = (const float*)d_in[5];
    const float* h_w   = (const float*)d_in[6];
    const float* h_b   = (const float*)d_in[7];
    const float* out_w = (const float*)d_in[8];
    const float* out_b = (const float*)d_in[9];
    float* out = (float*)d_out;

    float *pfT, *pgT, *ph, *pfcs, *pS, *psoff, *pmean, *pinv;
    cudaGetSymbolAddress((void**)&pfT,   d_fT);
    cudaGetSymbolAddress((void**)&pgT,   d_gT);
    cudaGetSymbolAddress((void**)&ph,    d_h);
    cudaGetSymbolAddress((void**)&pfcs,  d_fcs);
    cudaGetSymbolAddress((void**)&pS,    d_S);
    cudaGetSymbolAddress((void**)&psoff, d_soff);
    cudaGetSymbolAddress((void**)&pmean, d_mean);
    cudaGetSymbolAddress((void**)&pinv,  d_inv);

    const int SM_G = 4 * 128 * SROW * 4;                    // 73728 (2-stage A+B)
    const int SM_C = (2 * 128 * SROW + 2 * 32 * 132) * 4;   // 70656
    cudaFuncSetAttribute(mma_gemm<1, 0, 0>, cudaFuncAttributeMaxDynamicSharedMemorySize, SM_G);
    cudaFuncSetAttribute(mma_gemm<0, 0, 1>, cudaFuncAttributeMaxDynamicSharedMemorySize, SM_G);
    cudaFuncSetAttribute(mma_gemm<0, 1, 0>, cudaFuncAttributeMaxDynamicSharedMemorySize, SM_G);
    cudaFuncSetAttribute(conv_mma<1, 1>,    cudaFuncAttributeMaxDynamicSharedMemorySize, SM_C);
    cudaFuncSetAttribute(conv_mma<0, 0>,    cudaFuncAttributeMaxDynamicSharedMemorySize, SM_C);

    stats_kernel<<<dim3(BATCH * CIN, 2), 256>>>(Fc, Fs);

    // fT[n][d] = relu6(f_w @ mvn(Fc) + f_b)^T   (bf16 split)
    conv_mma<1, 1><<<dim3(NT / 128, CH / 128, BATCH), 256, SM_C>>>(
        f_w, Fc, f_b, pmean, pinv, pfT, CIN, CH, (size_t)NT * CH);
    // gT[m][d] = relu6(g_w @ mvn(Fs) + g_b)^T   (bf16 split)
    conv_mma<1, 1><<<dim3(NT / 128, CH / 128, BATCH), 256, SM_C>>>(
        g_w, Fs, g_b, pmean + BATCH * CIN, pinv + BATCH * CIN, pgT, CIN, CH, (size_t)NT * CH);
    // h[d][m] = relu6(h_w @ Fs + h_b)           (1xtf32)
    conv_mma<0, 0><<<dim3(NT / 128, CH / 128, BATCH), 256, SM_C>>>(
        h_w, Fs, h_b, nullptr, nullptr, ph, CIN, NT, (size_t)CH * NT);

    // S[n][m] = fT . gT^T   (bf16 split, 512 threads)
    mma_gemm<1, 0, 0><<<dim3(NT / 128, NT / 128, BATCH), 512, SM_G>>>(
        pfT, pgT, nullptr, nullptr, pS, CH, CH, CH, NT,
        (size_t)NT * CH, (size_t)NT * CH, (size_t)NT * NT);

    // per-row max + ln(sum exp)   (read-only pass)
    rowstat_kernel<<<BATCH * NT, 256>>>(pS, psoff);

    // fcs[n][d] = softmax(S) . h^T   (1xtf32, exp at A-tile store, 512 threads)
    mma_gemm<0, 0, 1><<<dim3(CH / 128, NT / 128, BATCH), 512, SM_G>>>(
        pS, ph, nullptr, psoff, pfcs, NT, NT, NT, CH,
        (size_t)NT * NT, (size_t)CH * NT, (size_t)NT * CH);

    // out[r][n] = relu6(out_w @ fcs^T + out_b)  (1xtf32, 512 threads)
    mma_gemm<0, 1, 0><<<dim3(NT / 128, CIN / 128, BATCH), 512, SM_G>>>(
        out_w, pfcs, out_b, nullptr, out, CH, CH, CH, NT,
        (size_t)0, (size_t)NT * CH, (size_t)CIN * NT);
}